// round 3
// baseline (speedup 1.0000x reference)
#include <cuda_runtime.h>

// Problem constants
#define NM 8          // sub-codebooks
#define NE 1024       // codes per sub-codebook
#define ED 64         // code dim
#define NQ 16384      // queries per sub-codebook (bs*h*w = 16*32*32)
#define KC 128        // codes per smem chunk

// Output layout (all float32): [z_vq | loss | indices | bin_count]
#define Z_ELEMS  8388608
#define LOSS_OFF 8388608
#define IDX_OFF  8388609
#define BIN_OFF  8519681   // IDX_OFF + NM*NQ
// total out = 8520705

// ---- packed f32x2 helpers (FFMA2: full-rate fp32 on sm_103a) ----
__device__ __forceinline__ unsigned long long pk2(float lo, float hi) {
    unsigned long long r;
    asm("mov.b64 %0, {%1,%2};" : "=l"(r) : "f"(lo), "f"(hi));
    return r;
}
__device__ __forceinline__ void fma2(unsigned long long& d,
                                     unsigned long long a,
                                     unsigned long long b) {
    asm("fma.rn.f32x2 %0, %1, %2, %0;" : "+l"(d) : "l"(a), "l"(b));
}
__device__ __forceinline__ float2 upk2(unsigned long long v) {
    float2 r;
    asm("mov.b64 {%0,%1}, %2;" : "=f"(r.x), "=f"(r.y) : "l"(v));
    return r;
}

// Zero the accumulated outputs (loss + bin_count) each launch — d_out is
// poisoned to 0xAA and we accumulate with atomics.
__global__ void vq_init(float* __restrict__ out) {
    int i = threadIdx.x;
    out[BIN_OFF + i] = 0.0f;
    if (i == 0) out[LOSS_OFF] = 0.0f;
}

// One block = 256 consecutive queries for one sub-codebook m.
// Each thread owns one query vector (64 floats, packed into 32 f32x2 regs),
// loops over all 1024 codes in 8 smem chunks of 128 codes.
__global__ void __launch_bounds__(256)
vq_main(const float* __restrict__ z,
        const float* __restrict__ cb,
        float* __restrict__ out) {
    const int m = blockIdx.x;
    const int n = blockIdx.y * 256 + threadIdx.x;

    // z index for (m, d, n): b*524288 + m*65536 + d*1024 + (n & 1023)
    const int b = n >> 10;
    const int rem = n & 1023;            // hh*32 + ww
    const int base = b * 524288 + m * 65536 + rem;

    // Load this thread's query vector (64 floats, stride 1024 per d; warp
    // lanes are consecutive `rem` -> each LDG is one coalesced 128B line).
    unsigned long long zp[32];
#pragma unroll
    for (int j = 0; j < 32; j++) {
        float lo = z[base + (2 * j) * 1024];
        float hi = z[base + (2 * j + 1) * 1024];
        zp[j] = pk2(lo, hi);
    }

    // Z = ||z||^2 in f32. Exact accumulation order is irrelevant: the
    // reference's distance d_k = RN(RN(Z+E_k) - 2*dot_k) has a quantized
    // offset from Z that is Z-independent within a binade, so any f32 Z in
    // the right binade reproduces the reference argmin ordering.
    float zn = 0.0f;
#pragma unroll
    for (int j = 0; j < 32; j++) {
        float2 v = upk2(zp[j]);
        zn += v.x * v.x;
        zn += v.y * v.y;
    }

    __shared__ float scb[KC * ED];   // 32 KB codebook chunk
    __shared__ float snorm[KC];      // ||e||^2 per code in chunk
    __shared__ float red[8];         // per-warp loss partials

    float best = 3.4e38f;
    int bestk = 0;

    const float* cbm = cb + m * (NE * ED);

    for (int c0 = 0; c0 < NE; c0 += KC) {
        __syncthreads();
        // cooperative chunk load (float4, fully coalesced)
        {
            const float4* src = (const float4*)(cbm + c0 * ED);
            float4* dst = (float4*)scb;
#pragma unroll
            for (int i = threadIdx.x; i < KC * ED / 4; i += 256)
                dst[i] = src[i];
        }
        __syncthreads();
        if (threadIdx.x < KC) {
            float s = 0.0f;
            const float* row = scb + threadIdx.x * ED;
#pragma unroll
            for (int d = 0; d < ED; d++) s += row[d] * row[d];
            snorm[threadIdx.x] = s;
        }
        __syncthreads();

        for (int k = 0; k < KC; k++) {
            // dot(z, code_k): 32 FFMA2 with 4-way accumulator ILP,
            // code row read as 16B LDS (warp-uniform -> broadcast, no conflicts)
            unsigned long long a0 = 0ull, a1 = 0ull, a2 = 0ull, a3 = 0ull;
            const ulonglong2* crow = (const ulonglong2*)(scb + k * ED);
#pragma unroll
            for (int j = 0; j < 8; j++) {
                ulonglong2 p0 = crow[2 * j];
                ulonglong2 p1 = crow[2 * j + 1];
                fma2(a0, zp[4 * j + 0], p0.x);
                fma2(a1, zp[4 * j + 1], p0.y);
                fma2(a2, zp[4 * j + 2], p1.x);
                fma2(a3, zp[4 * j + 3], p1.y);
            }
            float2 f0 = upk2(a0), f1 = upk2(a1), f2 = upk2(a2), f3 = upk2(a3);
            float dot = ((f0.x + f0.y) + (f1.x + f1.y)) +
                        ((f2.x + f2.y) + (f3.x + f3.y));
            // Replicate the reference's rounding sequence exactly:
            //   t = RN(Z + ||e_k||^2);  s = RN(t - 2*dot)   (2*dot is exact,
            // so the single-rounding fmaf equals RN(t - RN(2*dot))).
            float t = zn + snorm[k];
            float s = fmaf(-2.0f, dot, t);
            if (s < best) { best = s; bestk = c0 + k; }  // first-min tie-break
        }
    }

    // ---- epilogue: gather chosen code, write z_vq, indices, loss, bins ----
    const float4* code4 = (const float4*)(cbm + bestk * ED);
    float sq = 0.0f;
#pragma unroll
    for (int j = 0; j < 16; j++) {
        float4 c = code4[j];                 // 16B loads, codebook lives in L2
        float2 z0 = upk2(zp[2 * j]);
        float2 z1 = upk2(zp[2 * j + 1]);
        float d0 = c.x - z0.x, d1 = c.y - z0.y;
        float d2 = c.z - z1.x, d3 = c.w - z1.y;
        sq += d0 * d0 + d1 * d1 + d2 * d2 + d3 * d3;
        // z_vq has z's layout (straight-through forward value == zq)
        out[base + (4 * j + 0) * 1024] = c.x;
        out[base + (4 * j + 1) * 1024] = c.y;
        out[base + (4 * j + 2) * 1024] = c.z;
        out[base + (4 * j + 3) * 1024] = c.w;
    }

    out[IDX_OFF + m * NQ + n] = (float)bestk;
    atomicAdd(out + BIN_OFF + bestk, 1.0f);

    // loss = 1.25 * sum(diff^2) / (NQ*ED)   (codebook + beta*commit, values equal)
#pragma unroll
    for (int o = 16; o > 0; o >>= 1)
        sq += __shfl_down_sync(0xffffffffu, sq, o);
    if ((threadIdx.x & 31) == 0) red[threadIdx.x >> 5] = sq;
    __syncthreads();
    if (threadIdx.x == 0) {
        float s = 0.0f;
#pragma unroll
        for (int i = 0; i < 8; i++) s += red[i];
        atomicAdd(out + LOSS_OFF, s * (1.25f / (float)(NQ * ED)));
    }
}

extern "C" void kernel_launch(void* const* d_in, const int* in_sizes, int n_in,
                              void* d_out, int out_size) {
    const float* z  = (const float*)d_in[0];
    const float* cb = (const float*)d_in[1];
    float* out = (float*)d_out;

    vq_init<<<1, 1024>>>(out);
    dim3 grid(NM, NQ / 256);
    vq_main<<<grid, 256>>>(z, cb, out);
}

// round 5
// speedup vs baseline: 1.0498x; 1.0498x over previous
#include <cuda_runtime.h>

// Problem constants
#define NM 8          // sub-codebooks
#define NE 1024       // codes per sub-codebook
#define ED 64         // code dim
#define NQ 16384      // queries per sub-codebook (bs*h*w = 16*32*32)
#define KC 128        // codes per smem chunk

// Output layout (all float32): [z_vq | loss | indices | bin_count]
#define Z_ELEMS  8388608
#define LOSS_OFF 8388608
#define IDX_OFF  8388609
#define BIN_OFF  8519681   // IDX_OFF + NM*NQ
// total out = 8520705

// ---- packed f32x2 helpers (FFMA2: full-rate fp32 on sm_103a) ----
__device__ __forceinline__ unsigned long long pk2(float lo, float hi) {
    unsigned long long r;
    asm("mov.b64 %0, {%1,%2};" : "=l"(r) : "f"(lo), "f"(hi));
    return r;
}
__device__ __forceinline__ void fma2(unsigned long long& d,
                                     unsigned long long a,
                                     unsigned long long b) {
    asm("fma.rn.f32x2 %0, %1, %2, %0;" : "+l"(d) : "l"(a), "l"(b));
}
__device__ __forceinline__ float2 upk2(unsigned long long v) {
    float2 r;
    asm("mov.b64 {%0,%1}, %2;" : "=f"(r.x), "=f"(r.y) : "l"(v));
    return r;
}

// Zero the accumulated outputs (loss + bin_count) each launch — d_out is
// poisoned to 0xAA and we accumulate with atomics.
__global__ void vq_init(float* __restrict__ out) {
    int i = threadIdx.x;
    out[BIN_OFF + i] = 0.0f;
    if (i == 0) out[LOSS_OFF] = 0.0f;
}

// One block = 128 threads x 2 queries = 256 consecutive queries for one
// sub-codebook m. Each thread owns TWO query vectors in registers; each code
// row is loaded from smem ONCE per k and applied to both queries -> the
// LDS:FMA instruction ratio drops from 1:2 to 1:4, moving the kernel from
// LSU-issue-bound to FMA-pipe-bound.
__global__ void __launch_bounds__(128)
vq_main(const float* __restrict__ z,
        const float* __restrict__ cb,
        float* __restrict__ out) {
    const int m = blockIdx.x;
    const int tid = threadIdx.x;
    const int n0 = blockIdx.y * 256 + tid;        // query 0
    const int n1 = n0 + 128;                      // query 1

    // z index for (m, d, n): b*524288 + m*65536 + d*1024 + (n & 1023)
    const int base0 = (n0 >> 10) * 524288 + m * 65536 + (n0 & 1023);
    const int base1 = (n1 >> 10) * 524288 + m * 65536 + (n1 & 1023);

    // Load both query vectors (64 floats each, stride 1024 per d; warp lanes
    // are consecutive -> each LDG is one coalesced 128B line).
    unsigned long long zp0[32], zp1[32];
#pragma unroll
    for (int j = 0; j < 32; j++) {
        zp0[j] = pk2(z[base0 + (2 * j) * 1024], z[base0 + (2 * j + 1) * 1024]);
        zp1[j] = pk2(z[base1 + (2 * j) * 1024], z[base1 + (2 * j + 1) * 1024]);
    }

    // Z = ||z||^2 in f32. The reference distance d_k = RN(RN(Z+E_k) - 2*dot_k)
    // has a quantized offset from Z that is Z-independent within a binade, so
    // any f32 Z in the right binade reproduces the reference argmin ordering.
    float zn0 = 0.0f, zn1 = 0.0f;
#pragma unroll
    for (int j = 0; j < 32; j++) {
        float2 v0 = upk2(zp0[j]);
        float2 v1 = upk2(zp1[j]);
        zn0 += v0.x * v0.x; zn0 += v0.y * v0.y;
        zn1 += v1.x * v1.x; zn1 += v1.y * v1.y;
    }

    __shared__ float scb[KC * ED];   // 32 KB codebook chunk
    __shared__ float snorm[KC];      // ||e||^2 per code in chunk
    __shared__ float red[4];         // per-warp loss partials

    float best0 = 3.4e38f, best1 = 3.4e38f;
    int bestk0 = 0, bestk1 = 0;

    const float* cbm = cb + m * (NE * ED);

    for (int c0 = 0; c0 < NE; c0 += KC) {
        __syncthreads();
        // cooperative chunk load (float4, fully coalesced)
        {
            const float4* src = (const float4*)(cbm + c0 * ED);
            float4* dst = (float4*)scb;
#pragma unroll
            for (int i = tid; i < KC * ED / 4; i += 128)
                dst[i] = src[i];
        }
        __syncthreads();
        {
            float s = 0.0f;
            const float* row = scb + tid * ED;
#pragma unroll
            for (int d = 0; d < ED; d++) s += row[d] * row[d];
            snorm[tid] = s;
        }
        __syncthreads();

        for (int k = 0; k < KC; k++) {
            // code row read as 16B LDS, warp-uniform -> broadcast (N=1);
            // each loaded value feeds FMAs for BOTH queries.
            unsigned long long a0 = 0ull, a1 = 0ull, a2 = 0ull, a3 = 0ull;
            unsigned long long b0 = 0ull, b1 = 0ull, b2 = 0ull, b3 = 0ull;
            const ulonglong2* crow = (const ulonglong2*)(scb + k * ED);
#pragma unroll
            for (int j = 0; j < 8; j++) {
                ulonglong2 p0 = crow[2 * j];
                ulonglong2 p1 = crow[2 * j + 1];
                fma2(a0, zp0[4 * j + 0], p0.x);
                fma2(b0, zp1[4 * j + 0], p0.x);
                fma2(a1, zp0[4 * j + 1], p0.y);
                fma2(b1, zp1[4 * j + 1], p0.y);
                fma2(a2, zp0[4 * j + 2], p1.x);
                fma2(b2, zp1[4 * j + 2], p1.x);
                fma2(a3, zp0[4 * j + 3], p1.y);
                fma2(b3, zp1[4 * j + 3], p1.y);
            }
            float2 f0 = upk2(a0), f1 = upk2(a1), f2 = upk2(a2), f3 = upk2(a3);
            float dot0 = ((f0.x + f0.y) + (f1.x + f1.y)) +
                         ((f2.x + f2.y) + (f3.x + f3.y));
            float2 g0 = upk2(b0), g1 = upk2(b1), g2 = upk2(b2), g3 = upk2(b3);
            float dot1 = ((g0.x + g0.y) + (g1.x + g1.y)) +
                         ((g2.x + g2.y) + (g3.x + g3.y));
            // Replicate the reference rounding sequence exactly:
            //   t = RN(Z + ||e_k||^2);  s = RN(t - 2*dot)  (2*dot exact).
            float sk = snorm[k];
            float s0 = fmaf(-2.0f, dot0, zn0 + sk);
            float s1 = fmaf(-2.0f, dot1, zn1 + sk);
            if (s0 < best0) { best0 = s0; bestk0 = c0 + k; }
            if (s1 < best1) { best1 = s1; bestk1 = c0 + k; }
        }
    }

    // ---- epilogue: gather chosen codes, write z_vq, indices, loss, bins ----
    float sq = 0.0f;
    {
        const float4* code4 = (const float4*)(cbm + bestk0 * ED);
#pragma unroll
        for (int j = 0; j < 16; j++) {
            float4 c = code4[j];
            float2 q0 = upk2(zp0[2 * j]);
            float2 q1 = upk2(zp0[2 * j + 1]);
            float d0 = c.x - q0.x, d1 = c.y - q0.y;
            float d2 = c.z - q1.x, d3 = c.w - q1.y;
            sq += d0 * d0 + d1 * d1 + d2 * d2 + d3 * d3;
            out[base0 + (4 * j + 0) * 1024] = c.x;
            out[base0 + (4 * j + 1) * 1024] = c.y;
            out[base0 + (4 * j + 2) * 1024] = c.z;
            out[base0 + (4 * j + 3) * 1024] = c.w;
        }
    }
    {
        const float4* code4 = (const float4*)(cbm + bestk1 * ED);
#pragma unroll
        for (int j = 0; j < 16; j++) {
            float4 c = code4[j];
            float2 q0 = upk2(zp1[2 * j]);
            float2 q1 = upk2(zp1[2 * j + 1]);
            float d0 = c.x - q0.x, d1 = c.y - q0.y;
            float d2 = c.z - q1.x, d3 = c.w - q1.y;
            sq += d0 * d0 + d1 * d1 + d2 * d2 + d3 * d3;
            out[base1 + (4 * j + 0) * 1024] = c.x;
            out[base1 + (4 * j + 1) * 1024] = c.y;
            out[base1 + (4 * j + 2) * 1024] = c.z;
            out[base1 + (4 * j + 3) * 1024] = c.w;
        }
    }

    out[IDX_OFF + m * NQ + n0] = (float)bestk0;
    out[IDX_OFF + m * NQ + n1] = (float)bestk1;
    atomicAdd(out + BIN_OFF + bestk0, 1.0f);
    atomicAdd(out + BIN_OFF + bestk1, 1.0f);

    // loss = 1.25 * sum(diff^2) / (NQ*ED)   (codebook + beta*commit, equal)
#pragma unroll
    for (int o = 16; o > 0; o >>= 1)
        sq += __shfl_down_sync(0xffffffffu, sq, o);
    if ((tid & 31) == 0) red[tid >> 5] = sq;
    __syncthreads();
    if (tid == 0) {
        float s = (red[0] + red[1]) + (red[2] + red[3]);
        atomicAdd(out + LOSS_OFF, s * (1.25f / (float)(NQ * ED)));
    }
}

extern "C" void kernel_launch(void* const* d_in, const int* in_sizes, int n_in,
                              void* d_out, int out_size) {
    const float* z  = (const float*)d_in[0];
    const float* cb = (const float*)d_in[1];
    float* out = (float*)d_out;

    vq_init<<<1, 1024>>>(out);
    dim3 grid(NM, NQ / 256);
    vq_main<<<grid, 128>>>(z, cb, out);
}

// round 8
// speedup vs baseline: 1.1175x; 1.0646x over previous
#include <cuda_runtime.h>

// Problem constants
#define NM 8          // sub-codebooks
#define NE 1024       // codes per sub-codebook
#define ED 64         // code dim
#define NQ 16384      // queries per sub-codebook (bs*h*w = 16*32*32)
#define KC 128        // codes per smem chunk

// Output layout (all float32): [z_vq | loss | indices | bin_count]
#define Z_ELEMS  8388608
#define LOSS_OFF 8388608
#define IDX_OFF  8388609
#define BIN_OFF  8519681   // IDX_OFF + NM*NQ
// total out = 8520705

// ---- packed f32x2 helpers (FFMA2/FADD2: full-rate fp32 on sm_103a) ----
__device__ __forceinline__ unsigned long long pk2(float lo, float hi) {
    unsigned long long r;
    asm("mov.b64 %0, {%1,%2};" : "=l"(r) : "f"(lo), "f"(hi));
    return r;
}
__device__ __forceinline__ void fma2(unsigned long long& d,
                                     unsigned long long a,
                                     unsigned long long b) {
    asm("fma.rn.f32x2 %0, %1, %2, %0;" : "+l"(d) : "l"(a), "l"(b));
}
__device__ __forceinline__ void add2(unsigned long long& d,
                                     unsigned long long a) {
    asm("add.rn.f32x2 %0, %0, %1;" : "+l"(d) : "l"(a));
}
__device__ __forceinline__ float2 upk2(unsigned long long v) {
    float2 r;
    asm("mov.b64 {%0,%1}, %2;" : "=f"(r.x), "=f"(r.y) : "l"(v));
    return r;
}
// horizontal sum of 4 packed accumulators -> scalar
__device__ __forceinline__ float hsum4(unsigned long long a0,
                                       unsigned long long a1,
                                       unsigned long long a2,
                                       unsigned long long a3) {
    add2(a0, a1);
    add2(a2, a3);
    add2(a0, a2);
    float2 f = upk2(a0);
    return f.x + f.y;
}

// Zero the accumulated outputs (loss + bin_count) each launch — d_out is
// poisoned to 0xAA and we accumulate with atomics.
__global__ void vq_init(float* __restrict__ out) {
    int i = threadIdx.x;
    out[BIN_OFF + i] = 0.0f;
    if (i == 0) out[LOSS_OFF] = 0.0f;
}

// One block = 128 threads x 2 queries = 256 consecutive queries for one
// sub-codebook m. Each thread owns TWO query vectors in registers. The code
// loop is unrolled by 2 (two code rows in flight, 16 independent FFMA2
// accumulator chains) so each code's reduction tail overlaps the other
// code's FMA stream and LDS latency is hidden across bodies.
__global__ void __launch_bounds__(128)
vq_main(const float* __restrict__ z,
        const float* __restrict__ cb,
        float* __restrict__ out) {
    const int m = blockIdx.x;
    const int tid = threadIdx.x;
    const int n0 = blockIdx.y * 256 + tid;        // query 0
    const int n1 = n0 + 128;                      // query 1

    // z index for (m, d, n): b*524288 + m*65536 + d*1024 + (n & 1023)
    const int base0 = (n0 >> 10) * 524288 + m * 65536 + (n0 & 1023);
    const int base1 = (n1 >> 10) * 524288 + m * 65536 + (n1 & 1023);

    // Load both query vectors (64 floats each, stride 1024 per d; warp lanes
    // are consecutive -> each LDG is one coalesced 128B line).
    unsigned long long zp0[32], zp1[32];
#pragma unroll
    for (int j = 0; j < 32; j++) {
        zp0[j] = pk2(z[base0 + (2 * j) * 1024], z[base0 + (2 * j + 1) * 1024]);
        zp1[j] = pk2(z[base1 + (2 * j) * 1024], z[base1 + (2 * j + 1) * 1024]);
    }

    // Z = ||z||^2 in f32. The reference distance d_k = RN(RN(Z+E_k) - 2*dot_k)
    // has a quantized offset from Z that is Z-independent within a binade, so
    // any f32 Z in the right binade reproduces the reference argmin ordering.
    float zn0 = 0.0f, zn1 = 0.0f;
#pragma unroll
    for (int j = 0; j < 32; j++) {
        float2 v0 = upk2(zp0[j]);
        float2 v1 = upk2(zp1[j]);
        zn0 += v0.x * v0.x; zn0 += v0.y * v0.y;
        zn1 += v1.x * v1.x; zn1 += v1.y * v1.y;
    }

    __shared__ float scb[KC * ED];   // 32 KB codebook chunk
    __shared__ float snorm[KC];      // ||e||^2 per code in chunk
    __shared__ float red[4];         // per-warp loss partials

    float best0 = 3.4e38f, best1 = 3.4e38f;
    int bestk0 = 0, bestk1 = 0;

    const float* cbm = cb + m * (NE * ED);

    for (int c0 = 0; c0 < NE; c0 += KC) {
        __syncthreads();
        // cooperative chunk load (float4, fully coalesced)
        {
            const float4* src = (const float4*)(cbm + c0 * ED);
            float4* dst = (float4*)scb;
#pragma unroll
            for (int i = tid; i < KC * ED / 4; i += 128)
                dst[i] = src[i];
        }
        __syncthreads();
        {
            float s = 0.0f;
            const float* row = scb + tid * ED;
#pragma unroll
            for (int d = 0; d < ED; d++) s += row[d] * row[d];
            snorm[tid] = s;
        }
        __syncthreads();

        for (int k = 0; k < KC; k += 2) {
            // two code rows in flight; rows are warp-uniform -> LDS broadcast
            const ulonglong2* rA = (const ulonglong2*)(scb + k * ED);
            const ulonglong2* rB = (const ulonglong2*)(scb + (k + 1) * ED);
            float skA = snorm[k];
            float skB = snorm[k + 1];

            // 16 independent accumulator chains (2 queries x 2 codes x 4)
            unsigned long long a0 = 0ull, a1 = 0ull, a2 = 0ull, a3 = 0ull; // q0,kA
            unsigned long long b0 = 0ull, b1 = 0ull, b2 = 0ull, b3 = 0ull; // q1,kA
            unsigned long long c0r = 0ull, c1 = 0ull, c2 = 0ull, c3 = 0ull; // q0,kB
            unsigned long long d0 = 0ull, d1 = 0ull, d2 = 0ull, d3 = 0ull; // q1,kB
#pragma unroll
            for (int j = 0; j < 8; j++) {
                ulonglong2 pA0 = rA[2 * j];
                ulonglong2 pA1 = rA[2 * j + 1];
                ulonglong2 pB0 = rB[2 * j];
                ulonglong2 pB1 = rB[2 * j + 1];
                unsigned long long q00 = zp0[4 * j + 0], q01 = zp0[4 * j + 1];
                unsigned long long q02 = zp0[4 * j + 2], q03 = zp0[4 * j + 3];
                unsigned long long q10 = zp1[4 * j + 0], q11 = zp1[4 * j + 1];
                unsigned long long q12 = zp1[4 * j + 2], q13 = zp1[4 * j + 3];
                fma2(a0, q00, pA0.x); fma2(b0, q10, pA0.x);
                fma2(c0r, q00, pB0.x); fma2(d0, q10, pB0.x);
                fma2(a1, q01, pA0.y); fma2(b1, q11, pA0.y);
                fma2(c1, q01, pB0.y); fma2(d1, q11, pB0.y);
                fma2(a2, q02, pA1.x); fma2(b2, q12, pA1.x);
                fma2(c2, q02, pB1.x); fma2(d2, q12, pB1.x);
                fma2(a3, q03, pA1.y); fma2(b3, q13, pA1.y);
                fma2(c3, q03, pB1.y); fma2(d3, q13, pB1.y);
            }
            // packed reduction trees (short tails, overlap across the 4 dots)
            float dotA0 = hsum4(a0, a1, a2, a3);
            float dotA1 = hsum4(b0, b1, b2, b3);
            float dotB0 = hsum4(c0r, c1, c2, c3);
            float dotB1 = hsum4(d0, d1, d2, d3);
            // Replicate the reference rounding sequence exactly:
            //   t = RN(Z + ||e_k||^2);  s = RN(t - 2*dot)  (2*dot exact).
            float sA0 = fmaf(-2.0f, dotA0, zn0 + skA);
            float sA1 = fmaf(-2.0f, dotA1, zn1 + skA);
            float sB0 = fmaf(-2.0f, dotB0, zn0 + skB);
            float sB1 = fmaf(-2.0f, dotB1, zn1 + skB);
            // first-min tie-break: strictly-less, lower k checked first
            if (sA0 < best0) { best0 = sA0; bestk0 = c0 + k; }
            if (sB0 < best0) { best0 = sB0; bestk0 = c0 + k + 1; }
            if (sA1 < best1) { best1 = sA1; bestk1 = c0 + k; }
            if (sB1 < best1) { best1 = sB1; bestk1 = c0 + k + 1; }
        }
    }

    // ---- epilogue: gather chosen codes, write z_vq, indices, loss, bins ----
    float sq = 0.0f;
    {
        const float4* code4 = (const float4*)(cbm + bestk0 * ED);
#pragma unroll
        for (int j = 0; j < 16; j++) {
            float4 c = code4[j];
            float2 q0 = upk2(zp0[2 * j]);
            float2 q1 = upk2(zp0[2 * j + 1]);
            float d0 = c.x - q0.x, d1 = c.y - q0.y;
            float d2 = c.z - q1.x, d3 = c.w - q1.y;
            sq += d0 * d0 + d1 * d1 + d2 * d2 + d3 * d3;
            out[base0 + (4 * j + 0) * 1024] = c.x;
            out[base0 + (4 * j + 1) * 1024] = c.y;
            out[base0 + (4 * j + 2) * 1024] = c.z;
            out[base0 + (4 * j + 3) * 1024] = c.w;
        }
    }
    {
        const float4* code4 = (const float4*)(cbm + bestk1 * ED);
#pragma unroll
        for (int j = 0; j < 16; j++) {
            float4 c = code4[j];
            float2 q0 = upk2(zp1[2 * j]);
            float2 q1 = upk2(zp1[2 * j + 1]);
            float d0 = c.x - q0.x, d1 = c.y - q0.y;
            float d2 = c.z - q1.x, d3 = c.w - q1.y;
            sq += d0 * d0 + d1 * d1 + d2 * d2 + d3 * d3;
            out[base1 + (4 * j + 0) * 1024] = c.x;
            out[base1 + (4 * j + 1) * 1024] = c.y;
            out[base1 + (4 * j + 2) * 1024] = c.z;
            out[base1 + (4 * j + 3) * 1024] = c.w;
        }
    }

    out[IDX_OFF + m * NQ + n0] = (float)bestk0;
    out[IDX_OFF + m * NQ + n1] = (float)bestk1;
    atomicAdd(out + BIN_OFF + bestk0, 1.0f);
    atomicAdd(out + BIN_OFF + bestk1, 1.0f);

    // loss = 1.25 * sum(diff^2) / (NQ*ED)   (codebook + beta*commit, equal)
#pragma unroll
    for (int o = 16; o > 0; o >>= 1)
        sq += __shfl_down_sync(0xffffffffu, sq, o);
    if ((tid & 31) == 0) red[tid >> 5] = sq;
    __syncthreads();
    if (tid == 0) {
        float s = (red[0] + red[1]) + (red[2] + red[3]);
        atomicAdd(out + LOSS_OFF, s * (1.25f / (float)(NQ * ED)));
    }
}

extern "C" void kernel_launch(void* const* d_in, const int* in_sizes, int n_in,
                              void* d_out, int out_size) {
    const float* z  = (const float*)d_in[0];
    const float* cb = (const float*)d_in[1];
    float* out = (float*)d_out;

    vq_init<<<1, 1024>>>(out);
    dim3 grid(NM, NQ / 256);
    vq_main<<<grid, 128>>>(z, cb, out);
}

// round 11
// speedup vs baseline: 1.7502x; 1.5662x over previous
#include <cuda_runtime.h>
#include <cstdint>

typedef unsigned long long ull;

// Problem constants
#define NM 8
#define NE 1024
#define ED 64
#define NQ 16384

// Output layout (all float32): [z_vq | loss | indices | bin_count]
#define LOSS_OFF 8388608
#define IDX_OFF  8388609
#define BIN_OFF  8519681

// Dynamic smem: B fragment store (128 codes/stage), snorm, loss partials.
// Per code: 8 ks * 4 tg * 16B = 512B + 64B pad (bank-conflict break) = 576B.
#define CODE_STRIDE 576
#define SN_OFF   (128 * CODE_STRIDE)          // 73728
#define RED_OFF  (SN_OFF + 512)
#define SMEM_TOTAL (RED_OFF + 64)

__device__ __forceinline__ uint32_t tf32_rna(float v) {
    uint32_t u;
    asm("cvt.rna.tf32.f32 %0, %1;" : "=r"(u) : "f"(v));
    return u;
}

// m16n8k8 tf32 MMA, D/C f32. A row-major frag, B col-major frag.
__device__ __forceinline__ void mma8(float* d, const uint32_t* a,
                                     uint32_t b0, uint32_t b1) {
    asm("mma.sync.aligned.m16n8k8.row.col.f32.tf32.tf32.f32 "
        "{%0,%1,%2,%3}, {%4,%5,%6,%7}, {%8,%9}, {%0,%1,%2,%3};"
        : "+f"(d[0]), "+f"(d[1]), "+f"(d[2]), "+f"(d[3])
        : "r"(a[0]), "r"(a[1]), "r"(a[2]), "r"(a[3]), "r"(b0), "r"(b1));
}

// Zero the accumulated outputs (loss + bin_count) each launch.
__global__ void vq_init(float* __restrict__ out) {
    int i = threadIdx.x;
    out[BIN_OFF + i] = 0.0f;
    if (i == 0) out[LOSS_OFF] = 0.0f;
}

// CTA = (m, 256 queries). 8 warps; warp owns 32 queries (two m16 tiles).
// A (queries, tf32 hi+lo) persistent in registers; B (codes) staged in smem
// per 128-code chunk as packed {b0hi,b1hi,b0lo,b1lo} fragments.
__global__ void __launch_bounds__(256, 1)
vq_mma(const float* __restrict__ z,
       const float* __restrict__ cb,
       float* __restrict__ out) {
    extern __shared__ char smem[];
    float* snorm = (float*)(smem + SN_OFF);
    float* red   = (float*)(smem + RED_OFF);

    const int tid = threadIdx.x;
    const int warp = tid >> 5, lane = tid & 31;
    const int g = lane >> 2, tg = lane & 3;
    const int m = blockIdx.x;
    const int qb = blockIdx.y * 256 + warp * 32;
    const float* cbm = cb + m * (NE * ED);

    // row classes c = mt*2 + half: query row = qb + mt*16 + half*8 + g
    int zbase[4];
#pragma unroll
    for (int c = 0; c < 4; c++) {
        int q = qb + (c >> 1) * 16 + (c & 1) * 8 + g;
        zbase[c] = (q >> 10) * 524288 + m * 65536 + (q & 1023);
    }

    // ---- A fragments: tf32 hi/lo split, plus ||z||^2 partials ----
    // frag (mt, ks): a0=(row g, k=8ks+tg) a1=(g+8, k) a2=(g, k+4) a3=(g+8, k+4)
    uint32_t ah[2][8][4], al[2][8][4];
    float zn[4] = {0.f, 0.f, 0.f, 0.f};
#pragma unroll
    for (int ks = 0; ks < 8; ks++) {
        const int k1 = ks * 8 + tg, k2 = k1 + 4;
#pragma unroll
        for (int mt = 0; mt < 2; mt++) {
            float v00 = z[zbase[mt * 2 + 0] + k1 * 1024];
            float v10 = z[zbase[mt * 2 + 1] + k1 * 1024];
            float v01 = z[zbase[mt * 2 + 0] + k2 * 1024];
            float v11 = z[zbase[mt * 2 + 1] + k2 * 1024];
            zn[mt * 2 + 0] += v00 * v00; zn[mt * 2 + 0] += v01 * v01;
            zn[mt * 2 + 1] += v10 * v10; zn[mt * 2 + 1] += v11 * v11;
            uint32_t h;
            h = tf32_rna(v00); ah[mt][ks][0] = h;
            al[mt][ks][0] = tf32_rna(v00 - __uint_as_float(h));
            h = tf32_rna(v10); ah[mt][ks][1] = h;
            al[mt][ks][1] = tf32_rna(v10 - __uint_as_float(h));
            h = tf32_rna(v01); ah[mt][ks][2] = h;
            al[mt][ks][2] = tf32_rna(v01 - __uint_as_float(h));
            h = tf32_rna(v11); ah[mt][ks][3] = h;
            al[mt][ks][3] = tf32_rna(v11 - __uint_as_float(h));
        }
    }
    // full ||z||^2 per row class via quad reduce (f32 order free within binade)
#pragma unroll
    for (int c = 0; c < 4; c++) {
        zn[c] += __shfl_xor_sync(0xffffffffu, zn[c], 1);
        zn[c] += __shfl_xor_sync(0xffffffffu, zn[c], 2);
    }

    ull best[4] = {~0ull, ~0ull, ~0ull, ~0ull};
    const uint32_t lane_fb = (uint32_t)(g * CODE_STRIDE + tg * 16);

    for (int st = 0; st < 8; st++) {
        __syncthreads();   // prior epilogues done reading snorm / B smem free

        // ---- stage 128 codes: split hi/lo, pack fragments ----
#pragma unroll
        for (int i = 0; i < 16; i++) {
            int c = tid + 256 * i;
            int n = c >> 5, ks = (c >> 2) & 7, t4 = c & 3;
            const float* src = cbm + (st * 128 + n) * 64 + ks * 8 + t4;
            float v0 = src[0], v1 = src[4];
            uint32_t h0 = tf32_rna(v0), h1 = tf32_rna(v1);
            uint32_t l0 = tf32_rna(v0 - __uint_as_float(h0));
            uint32_t l1 = tf32_rna(v1 - __uint_as_float(h1));
            *(uint4*)(smem + n * CODE_STRIDE + ks * 64 + t4 * 16) =
                make_uint4(h0, h1, l0, l1);
        }
        // snorm from gmem in reference element order (deterministic)
        if (tid < 128) {
            const float4* row = (const float4*)(cbm + (st * 128 + tid) * 64);
            float s = 0.f;
#pragma unroll
            for (int j = 0; j < 16; j++) {
                float4 e = row[j];
                s += e.x * e.x; s += e.y * e.y;
                s += e.z * e.z; s += e.w * e.w;
            }
            snorm[tid] = s;
        }
        __syncthreads();

        // ---- 4 sub-chunks of 32 codes: MMA + fused argmin epilogue ----
#pragma unroll 1
        for (int sub = 0; sub < 4; sub++) {
            float acc[2][4][4];
#pragma unroll
            for (int mt = 0; mt < 2; mt++)
#pragma unroll
                for (int nt = 0; nt < 4; nt++)
#pragma unroll
                    for (int r = 0; r < 4; r++) acc[mt][nt][r] = 0.f;

#pragma unroll
            for (int ks = 0; ks < 8; ks++) {
#pragma unroll
                for (int nt = 0; nt < 4; nt++) {
                    // one LDS.128 = {b0hi,b1hi,b0lo,b1lo} for (code tile, ks)
                    uint4 f = *(const uint4*)(smem +
                        (sub * 32 + nt * 8) * CODE_STRIDE + lane_fb + ks * 64);
                    mma8(acc[0][nt], ah[0][ks], f.x, f.y);  // Ahi * Bhi
                    mma8(acc[1][nt], ah[1][ks], f.x, f.y);
                    mma8(acc[0][nt], ah[0][ks], f.z, f.w);  // Ahi * Blo
                    mma8(acc[1][nt], ah[1][ks], f.z, f.w);
                    mma8(acc[0][nt], al[0][ks], f.x, f.y);  // Alo * Bhi
                    mma8(acc[1][nt], al[1][ks], f.x, f.y);
                }
            }

            // epilogue: accum (mt,nt) -> rows (g, g+8), cols 2tg, 2tg+1
#pragma unroll
            for (int nt = 0; nt < 4; nt++) {
                float2 sn = *(const float2*)&snorm[sub * 32 + nt * 8 + 2 * tg];
                int kc = st * 128 + sub * 32 + nt * 8 + 2 * tg;
#pragma unroll
                for (int mt = 0; mt < 2; mt++) {
                    // reference rounding: t = RN(Z+E); s = RN(t - 2*dot)
                    float s0 = fmaf(-2.f, acc[mt][nt][0], zn[mt * 2 + 0] + sn.x);
                    float s1 = fmaf(-2.f, acc[mt][nt][1], zn[mt * 2 + 0] + sn.y);
                    float s2 = fmaf(-2.f, acc[mt][nt][2], zn[mt * 2 + 1] + sn.x);
                    float s3 = fmaf(-2.f, acc[mt][nt][3], zn[mt * 2 + 1] + sn.y);
                    ull p;  // s > 0 -> float bits order-monotone; low idx wins
                    p = ((ull)__float_as_uint(s0) << 32) | (unsigned)kc;
                    if (p < best[mt * 2 + 0]) best[mt * 2 + 0] = p;
                    p = ((ull)__float_as_uint(s1) << 32) | (unsigned)(kc + 1);
                    if (p < best[mt * 2 + 0]) best[mt * 2 + 0] = p;
                    p = ((ull)__float_as_uint(s2) << 32) | (unsigned)kc;
                    if (p < best[mt * 2 + 1]) best[mt * 2 + 1] = p;
                    p = ((ull)__float_as_uint(s3) << 32) | (unsigned)(kc + 1);
                    if (p < best[mt * 2 + 1]) best[mt * 2 + 1] = p;
                }
            }
        }
    }

    // ---- quad allreduce of the 4 row-class results ----
#pragma unroll
    for (int c = 0; c < 4; c++) {
        ull o = __shfl_xor_sync(0xffffffffu, best[c], 1);
        if (o < best[c]) best[c] = o;
        o = __shfl_xor_sync(0xffffffffu, best[c], 2);
        if (o < best[c]) best[c] = o;
    }

    // lane tg handles row class tg: gather code, write z_vq/idx/bins, loss
    const int myc = tg;
    const int q = qb + (myc >> 1) * 16 + (myc & 1) * 8 + g;
    const int base = zbase[myc];
    const int bk = (int)(unsigned)(best[myc] & 0xffffffffull);
    const float4* code4 = (const float4*)(cbm + bk * 64);
    float sq = 0.f;
#pragma unroll
    for (int j = 0; j < 16; j++) {
        float4 cv = code4[j];
        float z0 = z[base + (4 * j + 0) * 1024];
        float z1 = z[base + (4 * j + 1) * 1024];
        float z2 = z[base + (4 * j + 2) * 1024];
        float z3 = z[base + (4 * j + 3) * 1024];
        float d0 = cv.x - z0, d1 = cv.y - z1, d2 = cv.z - z2, d3 = cv.w - z3;
        sq += d0 * d0 + d1 * d1 + d2 * d2 + d3 * d3;
        out[base + (4 * j + 0) * 1024] = cv.x;
        out[base + (4 * j + 1) * 1024] = cv.y;
        out[base + (4 * j + 2) * 1024] = cv.z;
        out[base + (4 * j + 3) * 1024] = cv.w;
    }
    out[IDX_OFF + m * NQ + q] = (float)bk;
    atomicAdd(out + BIN_OFF + bk, 1.0f);

    // loss = 1.25 * sum(diff^2) / (NQ*ED)
#pragma unroll
    for (int o = 16; o > 0; o >>= 1)
        sq += __shfl_down_sync(0xffffffffu, sq, o);
    if (lane == 0) red[warp] = sq;
    __syncthreads();
    if (tid == 0) {
        float s = ((red[0] + red[1]) + (red[2] + red[3])) +
                  ((red[4] + red[5]) + (red[6] + red[7]));
        atomicAdd(out + LOSS_OFF, s * (1.25f / (float)(NQ * ED)));
    }
}

extern "C" void kernel_launch(void* const* d_in, const int* in_sizes, int n_in,
                              void* d_out, int out_size) {
    const float* z  = (const float*)d_in[0];
    const float* cb = (const float*)d_in[1];
    float* out = (float*)d_out;

    cudaFuncSetAttribute(vq_mma, cudaFuncAttributeMaxDynamicSharedMemorySize,
                         SMEM_TOTAL);
    vq_init<<<1, 1024>>>(out);
    dim3 grid(NM, NQ / 256);
    vq_mma<<<grid, 256, SMEM_TOTAL>>>(z, cb, out);
}

// round 12
// speedup vs baseline: 2.0446x; 1.1682x over previous
#include <cuda_runtime.h>
#include <cstdint>

typedef unsigned long long ull;

// Problem constants
#define NM 8
#define NE 1024
#define ED 64
#define NQ 16384

// Output layout (all float32): [z_vq | loss | indices | bin_count]
#define LOSS_OFF 8388608
#define IDX_OFF  8388609
#define BIN_OFF  8519681

// Prepacked B fragments: per code 32 x uint4 {b0hi,b1hi,b0lo,b1lo}
// layout: (code*32 + ks*4 + t4) uint4s. 8192 codes -> 4MB (lives in L2).
__device__ uint4  g_pack[NM * NE * 32];
__device__ float  g_snorm[NM * NE];

// smem staging: 128 codes/chunk, 576B stride (pad kills LDS bank conflicts)
#define CODE_STRIDE 576
#define BUF_SZ   (128 * CODE_STRIDE)          // 73728
#define RED_OFF  (2 * BUF_SZ)
#define SMEM_TOTAL (RED_OFF + 64)

__device__ __forceinline__ uint32_t tf32_rna(float v) {
    uint32_t u;
    asm("cvt.rna.tf32.f32 %0, %1;" : "=r"(u) : "f"(v));
    return u;
}
__device__ __forceinline__ uint32_t smem_u32(const void* p) {
    uint32_t a;
    asm("{ .reg .u64 t; cvta.to.shared.u64 t, %1; cvt.u32.u64 %0, t; }"
        : "=r"(a) : "l"(p));
    return a;
}
__device__ __forceinline__ void cp16(uint32_t dst, const void* src) {
    asm volatile("cp.async.cg.shared.global [%0], [%1], 16;"
                 :: "r"(dst), "l"(src));
}
#define CP_COMMIT() asm volatile("cp.async.commit_group;" ::: "memory")
#define CP_WAIT0()  asm volatile("cp.async.wait_group 0;" ::: "memory")

// m16n8k8 tf32 MMA, D/C f32. A row-major frag, B col-major frag.
__device__ __forceinline__ void mma8(float* d, const uint32_t* a,
                                     uint32_t b0, uint32_t b1) {
    asm("mma.sync.aligned.m16n8k8.row.col.f32.tf32.tf32.f32 "
        "{%0,%1,%2,%3}, {%4,%5,%6,%7}, {%8,%9}, {%0,%1,%2,%3};"
        : "+f"(d[0]), "+f"(d[1]), "+f"(d[2]), "+f"(d[3])
        : "r"(a[0]), "r"(a[1]), "r"(a[2]), "r"(a[3]), "r"(b0), "r"(b1));
}

// Zero the accumulated outputs (loss + bin_count) each launch.
__global__ void vq_init(float* __restrict__ out) {
    int i = threadIdx.x;
    out[BIN_OFF + i] = 0.0f;
    if (i == 0) out[LOSS_OFF] = 0.0f;
}

// Pack B fragments once per launch: thread -> (code n, ks, t4).
__global__ void vq_pack(const float* __restrict__ cb) {
    int idx = blockIdx.x * 256 + threadIdx.x;     // 8192*32 threads
    int n = idx >> 5, ks = (idx >> 2) & 7, t4 = idx & 3;
    const float* src = cb + n * 64 + ks * 8 + t4;
    float v0 = src[0], v1 = src[4];
    uint32_t h0 = tf32_rna(v0), h1 = tf32_rna(v1);
    uint32_t l0 = tf32_rna(v0 - __uint_as_float(h0));
    uint32_t l1 = tf32_rna(v1 - __uint_as_float(h1));
    g_pack[(ull)n * 32 + ks * 4 + t4] = make_uint4(h0, h1, l0, l1);
}

// snorm per code, reference element order (same as the passing R11 kernel).
__global__ void vq_snorm(const float* __restrict__ cb) {
    int n = blockIdx.x * 256 + threadIdx.x;       // 8192 threads
    const float4* row = (const float4*)(cb + n * 64);
    float s = 0.f;
#pragma unroll
    for (int j = 0; j < 16; j++) {
        float4 e = row[j];
        s += e.x * e.x; s += e.y * e.y;
        s += e.z * e.z; s += e.w * e.w;
    }
    g_snorm[n] = s;
}

// CTA = (m, 256 queries). 8 warps; warp owns 32 queries (two m16 tiles).
// A (tf32 hi+lo) persistent in registers; B fragments cp.async-staged from
// the prepacked global buffer with double buffering.
__global__ void __launch_bounds__(256, 1)
vq_mma(const float* __restrict__ z,
       const float* __restrict__ cb,
       float* __restrict__ out) {
    extern __shared__ char smem[];
    float* red = (float*)(smem + RED_OFF);
    const uint32_t sbase = smem_u32(smem);

    const int tid = threadIdx.x;
    const int warp = tid >> 5, lane = tid & 31;
    const int g = lane >> 2, tg = lane & 3;
    const int m = blockIdx.x;
    const int qb = blockIdx.y * 256 + warp * 32;
    const float* cbm = cb + m * (NE * ED);
    const float* snm = g_snorm + m * NE;

    // row classes c = mt*2 + half: query row = qb + mt*16 + half*8 + g
    int zbase[4];
#pragma unroll
    for (int c = 0; c < 4; c++) {
        int q = qb + (c >> 1) * 16 + (c & 1) * 8 + g;
        zbase[c] = (q >> 10) * 524288 + m * 65536 + (q & 1023);
    }

    // ---- prologue: start staging chunk 0 while building A fragments ----
    const uint4* packm = g_pack + (ull)m * NE * 32;
#pragma unroll
    for (int i = 0; i < 18; i++) {                 // 4608 16B-copies / 256 thr
        int c = tid + 256 * i;
        if (c < 4096) {
            int code = c >> 5, w = c & 31;
            cp16(sbase + code * CODE_STRIDE + w * 16, packm + c);
        }
    }
    CP_COMMIT();

    // ---- A fragments: tf32 hi/lo split, plus ||z||^2 partials ----
    uint32_t ah[2][8][4], al[2][8][4];
    float zn[4] = {0.f, 0.f, 0.f, 0.f};
#pragma unroll
    for (int ks = 0; ks < 8; ks++) {
        const int k1 = ks * 8 + tg, k2 = k1 + 4;
#pragma unroll
        for (int mt = 0; mt < 2; mt++) {
            float v00 = z[zbase[mt * 2 + 0] + k1 * 1024];
            float v10 = z[zbase[mt * 2 + 1] + k1 * 1024];
            float v01 = z[zbase[mt * 2 + 0] + k2 * 1024];
            float v11 = z[zbase[mt * 2 + 1] + k2 * 1024];
            zn[mt * 2 + 0] += v00 * v00; zn[mt * 2 + 0] += v01 * v01;
            zn[mt * 2 + 1] += v10 * v10; zn[mt * 2 + 1] += v11 * v11;
            uint32_t h;
            h = tf32_rna(v00); ah[mt][ks][0] = h;
            al[mt][ks][0] = tf32_rna(v00 - __uint_as_float(h));
            h = tf32_rna(v10); ah[mt][ks][1] = h;
            al[mt][ks][1] = tf32_rna(v10 - __uint_as_float(h));
            h = tf32_rna(v01); ah[mt][ks][2] = h;
            al[mt][ks][2] = tf32_rna(v01 - __uint_as_float(h));
            h = tf32_rna(v11); ah[mt][ks][3] = h;
            al[mt][ks][3] = tf32_rna(v11 - __uint_as_float(h));
        }
    }
#pragma unroll
    for (int c = 0; c < 4; c++) {      // quad reduce (order free within binade)
        zn[c] += __shfl_xor_sync(0xffffffffu, zn[c], 1);
        zn[c] += __shfl_xor_sync(0xffffffffu, zn[c], 2);
    }

    ull best[4] = {~0ull, ~0ull, ~0ull, ~0ull};
    const uint32_t lane_fb = (uint32_t)(g * CODE_STRIDE + tg * 16);

    for (int st = 0; st < 8; st++) {
        CP_WAIT0();            // chunk st landed
        __syncthreads();       // visible to all; prev buffer reads also done

        // prefetch chunk st+1 into the other buffer (overlaps with MMAs)
        if (st < 7) {
            const uint4* src = packm + (st + 1) * 128 * 32;
            uint32_t dst = sbase + ((st + 1) & 1) * BUF_SZ;
#pragma unroll
            for (int i = 0; i < 18; i++) {
                int c = tid + 256 * i;
                if (c < 4096) {
                    int code = c >> 5, w = c & 31;
                    cp16(dst + code * CODE_STRIDE + w * 16, src + c);
                }
            }
        }
        CP_COMMIT();           // (empty group when st==7 keeps wait legal)

        const char* buf = smem + (st & 1) * BUF_SZ;

#pragma unroll 1
        for (int sub = 0; sub < 4; sub++) {
            float acc[2][4][4];
#pragma unroll
            for (int mt = 0; mt < 2; mt++)
#pragma unroll
                for (int nt = 0; nt < 4; nt++)
#pragma unroll
                    for (int r = 0; r < 4; r++) acc[mt][nt][r] = 0.f;

#pragma unroll
            for (int ks = 0; ks < 8; ks++) {
                uint4 f[4];
#pragma unroll
                for (int nt = 0; nt < 4; nt++)
                    f[nt] = *(const uint4*)(buf +
                        (sub * 32 + nt * 8) * CODE_STRIDE + lane_fb + ks * 64);
                // pass-by-pass: dependent MMAs on one acc are 8 issues apart
#pragma unroll
                for (int nt = 0; nt < 4; nt++) {
                    mma8(acc[0][nt], ah[0][ks], f[nt].x, f[nt].y);
                    mma8(acc[1][nt], ah[1][ks], f[nt].x, f[nt].y);
                }
#pragma unroll
                for (int nt = 0; nt < 4; nt++) {
                    mma8(acc[0][nt], ah[0][ks], f[nt].z, f[nt].w);
                    mma8(acc[1][nt], ah[1][ks], f[nt].z, f[nt].w);
                }
#pragma unroll
                for (int nt = 0; nt < 4; nt++) {
                    mma8(acc[0][nt], al[0][ks], f[nt].x, f[nt].y);
                    mma8(acc[1][nt], al[1][ks], f[nt].x, f[nt].y);
                }
            }

            // epilogue: accum (mt,nt) -> rows (g, g+8), cols 2tg, 2tg+1
#pragma unroll
            for (int nt = 0; nt < 4; nt++) {
                int kc = st * 128 + sub * 32 + nt * 8 + 2 * tg;
                float2 sn = *(const float2*)&snm[kc];
#pragma unroll
                for (int mt = 0; mt < 2; mt++) {
                    // reference rounding: t = RN(Z+E); s = RN(t - 2*dot)
                    float s0 = fmaf(-2.f, acc[mt][nt][0], zn[mt * 2 + 0] + sn.x);
                    float s1 = fmaf(-2.f, acc[mt][nt][1], zn[mt * 2 + 0] + sn.y);
                    float s2 = fmaf(-2.f, acc[mt][nt][2], zn[mt * 2 + 1] + sn.x);
                    float s3 = fmaf(-2.f, acc[mt][nt][3], zn[mt * 2 + 1] + sn.y);
                    ull p;  // s > 0 -> float bits order-monotone; low idx wins
                    p = ((ull)__float_as_uint(s0) << 32) | (unsigned)kc;
                    if (p < best[mt * 2 + 0]) best[mt * 2 + 0] = p;
                    p = ((ull)__float_as_uint(s1) << 32) | (unsigned)(kc + 1);
                    if (p < best[mt * 2 + 0]) best[mt * 2 + 0] = p;
                    p = ((ull)__float_as_uint(s2) << 32) | (unsigned)kc;
                    if (p < best[mt * 2 + 1]) best[mt * 2 + 1] = p;
                    p = ((ull)__float_as_uint(s3) << 32) | (unsigned)(kc + 1);
                    if (p < best[mt * 2 + 1]) best[mt * 2 + 1] = p;
                }
            }
        }
        __syncthreads();       // done reading buf before it is re-staged
    }

    // ---- quad allreduce of the 4 row-class results ----
#pragma unroll
    for (int c = 0; c < 4; c++) {
        ull o = __shfl_xor_sync(0xffffffffu, best[c], 1);
        if (o < best[c]) best[c] = o;
        o = __shfl_xor_sync(0xffffffffu, best[c], 2);
        if (o < best[c]) best[c] = o;
    }

    // lane tg handles row class tg: gather code, write z_vq/idx/bins, loss
    const int myc = tg;
    const int q = qb + (myc >> 1) * 16 + (myc & 1) * 8 + g;
    const int base = zbase[myc];
    const int bk = (int)(unsigned)(best[myc] & 0xffffffffull);
    const float4* code4 = (const float4*)(cbm + bk * 64);
    float sq = 0.f;
#pragma unroll
    for (int j = 0; j < 16; j++) {
        float4 cv = code4[j];
        float z0 = z[base + (4 * j + 0) * 1024];
        float z1 = z[base + (4 * j + 1) * 1024];
        float z2 = z[base + (4 * j + 2) * 1024];
        float z3 = z[base + (4 * j + 3) * 1024];
        float d0 = cv.x - z0, d1 = cv.y - z1, d2 = cv.z - z2, d3 = cv.w - z3;
        sq += d0 * d0 + d1 * d1 + d2 * d2 + d3 * d3;
        out[base + (4 * j + 0) * 1024] = cv.x;
        out[base + (4 * j + 1) * 1024] = cv.y;
        out[base + (4 * j + 2) * 1024] = cv.z;
        out[base + (4 * j + 3) * 1024] = cv.w;
    }
    out[IDX_OFF + m * NQ + q] = (float)bk;
    atomicAdd(out + BIN_OFF + bk, 1.0f);

    // loss = 1.25 * sum(diff^2) / (NQ*ED)
#pragma unroll
    for (int o = 16; o > 0; o >>= 1)
        sq += __shfl_down_sync(0xffffffffu, sq, o);
    if (lane == 0) red[warp] = sq;
    __syncthreads();
    if (tid == 0) {
        float s = ((red[0] + red[1]) + (red[2] + red[3])) +
                  ((red[4] + red[5]) + (red[6] + red[7]));
        atomicAdd(out + LOSS_OFF, s * (1.25f / (float)(NQ * ED)));
    }
}

extern "C" void kernel_launch(void* const* d_in, const int* in_sizes, int n_in,
                              void* d_out, int out_size) {
    const float* z  = (const float*)d_in[0];
    const float* cb = (const float*)d_in[1];
    float* out = (float*)d_out;

    cudaFuncSetAttribute(vq_mma, cudaFuncAttributeMaxDynamicSharedMemorySize,
                         SMEM_TOTAL);
    vq_init<<<1, 1024>>>(out);
    vq_pack<<<NM * NE * 32 / 256, 256>>>(cb);
    vq_snorm<<<NM * NE / 256, 256>>>(cb);
    dim3 grid(NM, NQ / 256);
    vq_mma<<<grid, 256, SMEM_TOTAL>>>(z, cb, out);
}

// round 13
// speedup vs baseline: 2.3423x; 1.1456x over previous
#include <cuda_runtime.h>
#include <cstdint>

typedef unsigned long long ull;

// Problem constants
#define NM 8
#define NE 1024
#define ED 64
#define NQ 16384

// Output layout (all float32): [z_vq | loss | indices | bin_count]
#define LOSS_OFF 8388608
#define IDX_OFF  8388609
#define BIN_OFF  8519681

// Prepacked B fragments: per code 32 x uint4 {b0hi,b1hi,b0lo,b1lo}
// layout: (code*32 + ks*4 + t4) uint4s. 8192 codes -> 4MB (lives in L2).
__device__ uint4  g_pack[NM * NE * 32];
__device__ float  g_snorm[NM * NE];

// smem staging: 64 codes/chunk, 576B stride (pad kills LDS bank conflicts)
#define CHUNK 64
#define CODE_STRIDE 576
#define BUF_SZ   (CHUNK * CODE_STRIDE)        // 36864
#define RED_OFF  (2 * BUF_SZ)
#define SMEM_TOTAL (RED_OFF + 64)

__device__ __forceinline__ uint32_t tf32_rna(float v) {
    uint32_t u;
    asm("cvt.rna.tf32.f32 %0, %1;" : "=r"(u) : "f"(v));
    return u;
}
__device__ __forceinline__ uint32_t smem_u32(const void* p) {
    uint32_t a;
    asm("{ .reg .u64 t; cvta.to.shared.u64 t, %1; cvt.u32.u64 %0, t; }"
        : "=r"(a) : "l"(p));
    return a;
}
__device__ __forceinline__ void cp16(uint32_t dst, const void* src) {
    asm volatile("cp.async.cg.shared.global [%0], [%1], 16;"
                 :: "r"(dst), "l"(src));
}
#define CP_COMMIT() asm volatile("cp.async.commit_group;" ::: "memory")
#define CP_WAIT0()  asm volatile("cp.async.wait_group 0;" ::: "memory")

// m16n8k8 tf32 MMA, D/C f32. A row-major frag, B col-major frag.
__device__ __forceinline__ void mma8(float* d, const uint32_t* a,
                                     uint32_t b0, uint32_t b1) {
    asm("mma.sync.aligned.m16n8k8.row.col.f32.tf32.tf32.f32 "
        "{%0,%1,%2,%3}, {%4,%5,%6,%7}, {%8,%9}, {%0,%1,%2,%3};"
        : "+f"(d[0]), "+f"(d[1]), "+f"(d[2]), "+f"(d[3])
        : "r"(a[0]), "r"(a[1]), "r"(a[2]), "r"(a[3]), "r"(b0), "r"(b1));
}

// Zero the accumulated outputs (loss + bin_count) each launch.
__global__ void vq_init(float* __restrict__ out) {
    int i = threadIdx.x;
    out[BIN_OFF + i] = 0.0f;
    if (i == 0) out[LOSS_OFF] = 0.0f;
}

// Pack B fragments once per launch: thread -> (code n, ks, t4).
__global__ void vq_pack(const float* __restrict__ cb) {
    int idx = blockIdx.x * 256 + threadIdx.x;     // 8192*32 threads
    int n = idx >> 5, ks = (idx >> 2) & 7, t4 = idx & 3;
    const float* src = cb + n * 64 + ks * 8 + t4;
    float v0 = src[0], v1 = src[4];
    uint32_t h0 = tf32_rna(v0), h1 = tf32_rna(v1);
    uint32_t l0 = tf32_rna(v0 - __uint_as_float(h0));
    uint32_t l1 = tf32_rna(v1 - __uint_as_float(h1));
    g_pack[(ull)n * 32 + ks * 4 + t4] = make_uint4(h0, h1, l0, l1);
}

// snorm per code, reference element order.
__global__ void vq_snorm(const float* __restrict__ cb) {
    int n = blockIdx.x * 256 + threadIdx.x;       // 8192 threads
    const float4* row = (const float4*)(cb + n * 64);
    float s = 0.f;
#pragma unroll
    for (int j = 0; j < 16; j++) {
        float4 e = row[j];
        s += e.x * e.x; s += e.y * e.y;
        s += e.z * e.z; s += e.w * e.w;
    }
    g_snorm[n] = s;
}

// CTA = (m, 128 queries). 8 warps; warp owns 16 queries (ONE m16 tile).
// launch_bounds(256,2) caps regs at 128 -> 2 CTAs/SM -> 4 warps/SMSP so
// epilogue ALU and HMMA dependency tails overlap other warps' MMA streams.
__global__ void __launch_bounds__(256, 2)
vq_mma(const float* __restrict__ z,
       const float* __restrict__ cb,
       float* __restrict__ out) {
    extern __shared__ char smem[];
    float* red = (float*)(smem + RED_OFF);
    const uint32_t sbase = smem_u32(smem);

    const int tid = threadIdx.x;
    const int warp = tid >> 5, lane = tid & 31;
    const int g = lane >> 2, tg = lane & 3;
    const int m = blockIdx.x;
    const int qb = blockIdx.y * 128 + warp * 16;
    const float* cbm = cb + m * (NE * ED);
    const float* snm = g_snorm + m * NE;

    // row classes c: query row = qb + c*8 + g   (c = 0,1)
    int zbase[2];
#pragma unroll
    for (int c = 0; c < 2; c++) {
        int q = qb + c * 8 + g;
        zbase[c] = (q >> 10) * 524288 + m * 65536 + (q & 1023);
    }

    // ---- prologue: start staging chunk 0 while building A fragments ----
    const uint4* packm = g_pack + (ull)m * NE * 32;
#pragma unroll
    for (int i = 0; i < 8; i++) {                  // 2048 16B-copies / 256 thr
        int c = tid + 256 * i;
        int code = c >> 5, w = c & 31;
        cp16(sbase + code * CODE_STRIDE + w * 16, packm + c);
    }
    CP_COMMIT();

    // ---- A fragments: tf32 hi/lo split, plus ||z||^2 partials ----
    // frag(ks): a0=(row g, k=8ks+tg) a1=(g+8, k) a2=(g, k+4) a3=(g+8, k+4)
    uint32_t ah[8][4], al[8][4];
    float zn[2] = {0.f, 0.f};
#pragma unroll
    for (int ks = 0; ks < 8; ks++) {
        const int k1 = ks * 8 + tg, k2 = k1 + 4;
        float v00 = z[zbase[0] + k1 * 1024];
        float v10 = z[zbase[1] + k1 * 1024];
        float v01 = z[zbase[0] + k2 * 1024];
        float v11 = z[zbase[1] + k2 * 1024];
        zn[0] += v00 * v00; zn[0] += v01 * v01;
        zn[1] += v10 * v10; zn[1] += v11 * v11;
        uint32_t h;
        h = tf32_rna(v00); ah[ks][0] = h;
        al[ks][0] = tf32_rna(v00 - __uint_as_float(h));
        h = tf32_rna(v10); ah[ks][1] = h;
        al[ks][1] = tf32_rna(v10 - __uint_as_float(h));
        h = tf32_rna(v01); ah[ks][2] = h;
        al[ks][2] = tf32_rna(v01 - __uint_as_float(h));
        h = tf32_rna(v11); ah[ks][3] = h;
        al[ks][3] = tf32_rna(v11 - __uint_as_float(h));
    }
#pragma unroll
    for (int c = 0; c < 2; c++) {      // quad reduce (order free within binade)
        zn[c] += __shfl_xor_sync(0xffffffffu, zn[c], 1);
        zn[c] += __shfl_xor_sync(0xffffffffu, zn[c], 2);
    }

    ull best[2] = {~0ull, ~0ull};
    const uint32_t lane_fb = (uint32_t)(g * CODE_STRIDE + tg * 16);

    for (int st = 0; st < 16; st++) {
        CP_WAIT0();            // chunk st landed
        __syncthreads();       // visible to all; prev buffer reads also done

        // prefetch chunk st+1 into the other buffer (overlaps with MMAs)
        if (st < 15) {
            const uint4* src = packm + (st + 1) * CHUNK * 32;
            uint32_t dst = sbase + ((st + 1) & 1) * BUF_SZ;
#pragma unroll
            for (int i = 0; i < 8; i++) {
                int c = tid + 256 * i;
                int code = c >> 5, w = c & 31;
                cp16(dst + code * CODE_STRIDE + w * 16, src + c);
            }
        }
        CP_COMMIT();           // (empty group when st==15 keeps wait legal)

        const char* buf = smem + (st & 1) * BUF_SZ;

#pragma unroll 1
        for (int sub = 0; sub < 2; sub++) {
            float acc[4][4];
#pragma unroll
            for (int nt = 0; nt < 4; nt++)
#pragma unroll
                for (int r = 0; r < 4; r++) acc[nt][r] = 0.f;

#pragma unroll
            for (int ks = 0; ks < 8; ks++) {
                uint4 f[4];
#pragma unroll
                for (int nt = 0; nt < 4; nt++)
                    f[nt] = *(const uint4*)(buf +
                        (sub * 32 + nt * 8) * CODE_STRIDE + lane_fb + ks * 64);
                // pass-by-pass: dependent MMAs on one acc are 4 issues apart
#pragma unroll
                for (int nt = 0; nt < 4; nt++)
                    mma8(acc[nt], ah[ks], f[nt].x, f[nt].y);   // Ahi*Bhi
#pragma unroll
                for (int nt = 0; nt < 4; nt++)
                    mma8(acc[nt], ah[ks], f[nt].z, f[nt].w);   // Ahi*Blo
#pragma unroll
                for (int nt = 0; nt < 4; nt++)
                    mma8(acc[nt], al[ks], f[nt].x, f[nt].y);   // Alo*Bhi
            }

            // epilogue: acc[nt] -> rows (g, g+8), cols 2tg, 2tg+1
#pragma unroll
            for (int nt = 0; nt < 4; nt++) {
                int kc = st * CHUNK + sub * 32 + nt * 8 + 2 * tg;
                float2 sn = *(const float2*)&snm[kc];
                // reference rounding: t = RN(Z+E); s = RN(t - 2*dot)
                float s0 = fmaf(-2.f, acc[nt][0], zn[0] + sn.x);
                float s1 = fmaf(-2.f, acc[nt][1], zn[0] + sn.y);
                float s2 = fmaf(-2.f, acc[nt][2], zn[1] + sn.x);
                float s3 = fmaf(-2.f, acc[nt][3], zn[1] + sn.y);
                ull p;  // s > 0 -> float bits order-monotone; low idx wins
                p = ((ull)__float_as_uint(s0) << 32) | (unsigned)kc;
                if (p < best[0]) best[0] = p;
                p = ((ull)__float_as_uint(s1) << 32) | (unsigned)(kc + 1);
                if (p < best[0]) best[0] = p;
                p = ((ull)__float_as_uint(s2) << 32) | (unsigned)kc;
                if (p < best[1]) best[1] = p;
                p = ((ull)__float_as_uint(s3) << 32) | (unsigned)(kc + 1);
                if (p < best[1]) best[1] = p;
            }
        }
        __syncthreads();       // done reading buf before it is re-staged
    }

    // ---- quad allreduce of the 2 row-class results ----
#pragma unroll
    for (int c = 0; c < 2; c++) {
        ull o = __shfl_xor_sync(0xffffffffu, best[c], 1);
        if (o < best[c]) best[c] = o;
        o = __shfl_xor_sync(0xffffffffu, best[c], 2);
        if (o < best[c]) best[c] = o;
    }

    // lanes tg<2 write outputs: lane handles row class tg (query qb+tg*8+g)
    float sq = 0.f;
    if (tg < 2) {
        const int q = qb + tg * 8 + g;
        const int base = zbase[tg];
        const int bk = (int)(unsigned)(best[tg] & 0xffffffffull);
        const float4* code4 = (const float4*)(cbm + bk * 64);
#pragma unroll
        for (int j = 0; j < 16; j++) {
            float4 cv = code4[j];
            float z0 = z[base + (4 * j + 0) * 1024];
            float z1 = z[base + (4 * j + 1) * 1024];
            float z2 = z[base + (4 * j + 2) * 1024];
            float z3 = z[base + (4 * j + 3) * 1024];
            float d0 = cv.x - z0, d1 = cv.y - z1, d2 = cv.z - z2, d3 = cv.w - z3;
            sq += d0 * d0 + d1 * d1 + d2 * d2 + d3 * d3;
            out[base + (4 * j + 0) * 1024] = cv.x;
            out[base + (4 * j + 1) * 1024] = cv.y;
            out[base + (4 * j + 2) * 1024] = cv.z;
            out[base + (4 * j + 3) * 1024] = cv.w;
        }
        out[IDX_OFF + m * NQ + q] = (float)bk;
        atomicAdd(out + BIN_OFF + bk, 1.0f);
    }

    // loss = 1.25 * sum(diff^2) / (NQ*ED)
#pragma unroll
    for (int o = 16; o > 0; o >>= 1)
        sq += __shfl_down_sync(0xffffffffu, sq, o);
    if (lane == 0) red[warp] = sq;
    __syncthreads();
    if (tid == 0) {
        float s = ((red[0] + red[1]) + (red[2] + red[3])) +
                  ((red[4] + red[5]) + (red[6] + red[7]));
        atomicAdd(out + LOSS_OFF, s * (1.25f / (float)(NQ * ED)));
    }
}

extern "C" void kernel_launch(void* const* d_in, const int* in_sizes, int n_in,
                              void* d_out, int out_size) {
    const float* z  = (const float*)d_in[0];
    const float* cb = (const float*)d_in[1];
    float* out = (float*)d_out;

    cudaFuncSetAttribute(vq_mma, cudaFuncAttributeMaxDynamicSharedMemorySize,
                         SMEM_TOTAL);
    vq_init<<<1, 1024>>>(out);
    vq_pack<<<NM * NE * 32 / 256, 256>>>(cb);
    vq_snorm<<<NM * NE / 256, 256>>>(cb);
    dim3 grid(NM, NQ / 128);
    vq_mma<<<grid, 256, SMEM_TOTAL>>>(z, cb, out);
}

// round 14
// speedup vs baseline: 3.5384x; 1.5106x over previous
#include <cuda_runtime.h>
#include <cuda_fp16.h>
#include <cstdint>

typedef unsigned long long ull;

// Problem constants
#define NM 8
#define NE 1024
#define ED 64
#define NQ 16384

// Output layout (all float32): [z_vq | loss | indices | bin_count]
#define LOSS_OFF 8388608
#define IDX_OFF  8388609
#define BIN_OFF  8519681

// Prepacked B fragments (fp16 emulation, scaled):
//   bh = fp16(B*2^6), bl' = fp16((B*2^6 - bh)*2^11)
// per code: 2 uint4 bh frags + 2 uint4 bl' frags per tg -> 256B + 16B pad.
#define CODE_STRIDE 272
__device__ uint4  g_pack[NM * NE * (CODE_STRIDE / 16)];
__device__ float  g_snorm[NM * NE];

// smem staging: 64 codes/chunk, double buffered
#define CHUNK 64
#define BUF_SZ   (CHUNK * CODE_STRIDE)        // 17408
#define RED_OFF  (2 * BUF_SZ)
#define SMEM_TOTAL (RED_OFF + 64)

__device__ __forceinline__ uint32_t pkh2(float a, float b) {
    __half2 h = __floats2half2_rn(a, b);      // low half = a (even k)
    return *reinterpret_cast<uint32_t*>(&h);
}
__device__ __forceinline__ uint32_t pkl2(float a, float b) {
    float ha = __half2float(__float2half_rn(a));
    float hb = __half2float(__float2half_rn(b));
    return pkh2((a - ha) * 2048.0f, (b - hb) * 2048.0f);
}
__device__ __forceinline__ uint32_t smem_u32(const void* p) {
    uint32_t a;
    asm("{ .reg .u64 t; cvta.to.shared.u64 t, %1; cvt.u32.u64 %0, t; }"
        : "=r"(a) : "l"(p));
    return a;
}
__device__ __forceinline__ void cp16(uint32_t dst, const void* src) {
    asm volatile("cp.async.cg.shared.global [%0], [%1], 16;"
                 :: "r"(dst), "l"(src));
}
#define CP_COMMIT() asm volatile("cp.async.commit_group;" ::: "memory")
#define CP_WAIT0()  asm volatile("cp.async.wait_group 0;" ::: "memory")

// m16n8k16 fp16 MMA, f32 accum. A row-major frag, B col-major frag.
__device__ __forceinline__ void mma16(float* d, const uint32_t* a,
                                      uint32_t b0, uint32_t b1) {
    asm("mma.sync.aligned.m16n8k16.row.col.f32.f16.f16.f32 "
        "{%0,%1,%2,%3}, {%4,%5,%6,%7}, {%8,%9}, {%0,%1,%2,%3};"
        : "+f"(d[0]), "+f"(d[1]), "+f"(d[2]), "+f"(d[3])
        : "r"(a[0]), "r"(a[1]), "r"(a[2]), "r"(a[3]), "r"(b0), "r"(b1));
}

// Zero the accumulated outputs (loss + bin_count) each launch.
__global__ void vq_init(float* __restrict__ out) {
    int i = threadIdx.x;
    out[BIN_OFF + i] = 0.0f;
    if (i == 0) out[LOSS_OFF] = 0.0f;
}

// Pack B fragments once per launch: thread -> (code n, tg).
__global__ void vq_pack(const float* __restrict__ cb) {
    int idx = blockIdx.x * 256 + threadIdx.x;     // NM*NE*4 threads
    int n = idx >> 2, tg = idx & 3;
    const float* B = cb + n * 64;
    uint32_t bh[8], bl[8];
#pragma unroll
    for (int c = 0; c < 4; c++) {
        float x0 = B[c * 16 + 2 * tg + 0] * 64.0f;
        float x1 = B[c * 16 + 2 * tg + 1] * 64.0f;
        float x2 = B[c * 16 + 2 * tg + 8] * 64.0f;
        float x3 = B[c * 16 + 2 * tg + 9] * 64.0f;
        bh[2 * c + 0] = pkh2(x0, x1); bh[2 * c + 1] = pkh2(x2, x3);
        bl[2 * c + 0] = pkl2(x0, x1); bl[2 * c + 1] = pkl2(x2, x3);
    }
    char* dst = (char*)g_pack + n * CODE_STRIDE + tg * 32;
    *(uint4*)(dst +   0) = make_uint4(bh[0], bh[1], bh[2], bh[3]);
    *(uint4*)(dst +  16) = make_uint4(bh[4], bh[5], bh[6], bh[7]);
    *(uint4*)(dst + 128) = make_uint4(bl[0], bl[1], bl[2], bl[3]);
    *(uint4*)(dst + 144) = make_uint4(bl[4], bl[5], bl[6], bl[7]);
}

// snorm per code, reference element order.
__global__ void vq_snorm(const float* __restrict__ cb) {
    int n = blockIdx.x * 256 + threadIdx.x;       // 8192 threads
    const float4* row = (const float4*)(cb + n * 64);
    float s = 0.f;
#pragma unroll
    for (int j = 0; j < 16; j++) {
        float4 e = row[j];
        s += e.x * e.x; s += e.y * e.y;
        s += e.z * e.z; s += e.w * e.w;
    }
    g_snorm[n] = s;
}

// CTA = (m, 128 queries). 8 warps; warp owns 16 queries (one m16 tile).
// 3-term fp16 emulation: main = zh*bh' (scale 2^-6), corr = zh*bl' + zl'*bh'
// (scale 2^-17), dot = fmaf(corr, 2^-17, main*2^-6).
__global__ void __launch_bounds__(256, 2)
vq_mma(const float* __restrict__ z,
       const float* __restrict__ cb,
       float* __restrict__ out) {
    extern __shared__ char smem[];
    float* red = (float*)(smem + RED_OFF);
    const uint32_t sbase = smem_u32(smem);

    const int tid = threadIdx.x;
    const int warp = tid >> 5, lane = tid & 31;
    const int g = lane >> 2, tg = lane & 3;
    const int m = blockIdx.x;
    const int qb = blockIdx.y * 128 + warp * 16;
    const float* cbm = cb + m * (NE * ED);
    const float* snm = g_snorm + m * NE;

    // row classes c: query row = qb + c*8 + g   (c = 0,1)
    int zbase[2];
#pragma unroll
    for (int c = 0; c < 2; c++) {
        int q = qb + c * 8 + g;
        zbase[c] = (q >> 10) * 524288 + m * 65536 + (q & 1023);
    }

    // ---- prologue: start staging chunk 0 (layout identical gmem->smem) ----
    const uint4* packm = g_pack + m * NE * (CODE_STRIDE / 16);
#pragma unroll
    for (int i = 0; i < 5; i++) {                  // 1088 16B-copies / 256 thr
        int c = tid + 256 * i;
        if (c < CHUNK * CODE_STRIDE / 16)
            cp16(sbase + c * 16, packm + c);
    }
    CP_COMMIT();

    // ---- A fragments: fp16 hi + scaled-lo split, plus ||z||^2 partials ----
    // chunk c covers k in [16c,16c+16): a0=(row g, k=16c+2tg,+1) a1=(g+8,same)
    //                                   a2=(g, k+8,+9) a3=(g+8, k+8,+9)
    uint32_t zh[4][4], zl[4][4];
    float zn[2] = {0.f, 0.f};
#pragma unroll
    for (int c = 0; c < 4; c++) {
        const int kA = c * 16 + 2 * tg;
        float v00 = z[zbase[0] + (kA + 0) * 1024];
        float v01 = z[zbase[0] + (kA + 1) * 1024];
        float v02 = z[zbase[0] + (kA + 8) * 1024];
        float v03 = z[zbase[0] + (kA + 9) * 1024];
        float v10 = z[zbase[1] + (kA + 0) * 1024];
        float v11 = z[zbase[1] + (kA + 1) * 1024];
        float v12 = z[zbase[1] + (kA + 8) * 1024];
        float v13 = z[zbase[1] + (kA + 9) * 1024];
        zn[0] += v00 * v00; zn[0] += v01 * v01;
        zn[0] += v02 * v02; zn[0] += v03 * v03;
        zn[1] += v10 * v10; zn[1] += v11 * v11;
        zn[1] += v12 * v12; zn[1] += v13 * v13;
        zh[c][0] = pkh2(v00, v01); zh[c][1] = pkh2(v10, v11);
        zh[c][2] = pkh2(v02, v03); zh[c][3] = pkh2(v12, v13);
        zl[c][0] = pkl2(v00, v01); zl[c][1] = pkl2(v10, v11);
        zl[c][2] = pkl2(v02, v03); zl[c][3] = pkl2(v12, v13);
    }
#pragma unroll
    for (int c = 0; c < 2; c++) {      // quad reduce (order free within binade)
        zn[c] += __shfl_xor_sync(0xffffffffu, zn[c], 1);
        zn[c] += __shfl_xor_sync(0xffffffffu, zn[c], 2);
    }

    ull best[2] = {~0ull, ~0ull};
    const uint32_t lane_fb = (uint32_t)(g * CODE_STRIDE + tg * 32);

    for (int st = 0; st < 16; st++) {
        CP_WAIT0();            // chunk st landed
        __syncthreads();       // visible to all; prev buffer reads also done

        // prefetch chunk st+1 into the other buffer (overlaps with MMAs)
        if (st < 15) {
            const uint4* src = packm + (st + 1) * CHUNK * (CODE_STRIDE / 16);
            uint32_t dst = sbase + ((st + 1) & 1) * BUF_SZ;
#pragma unroll
            for (int i = 0; i < 5; i++) {
                int c = tid + 256 * i;
                if (c < CHUNK * CODE_STRIDE / 16)
                    cp16(dst + c * 16, src + c);
            }
        }
        CP_COMMIT();           // (empty group when st==15 keeps wait legal)

        const char* buf = smem + (st & 1) * BUF_SZ;

#pragma unroll 1
        for (int sub = 0; sub < 4; sub++) {        // 16 codes per sub
            float am[2][4], ac[2][4];
#pragma unroll
            for (int nt = 0; nt < 2; nt++)
#pragma unroll
                for (int r = 0; r < 4; r++) { am[nt][r] = 0.f; ac[nt][r] = 0.f; }

            uint4 h0[2], h1[2], l0[2], l1[2];
#pragma unroll
            for (int nt = 0; nt < 2; nt++) {
                const char* p = buf + (sub * 16 + nt * 8) * CODE_STRIDE + lane_fb;
                h0[nt] = *(const uint4*)(p +   0);   // bh chunks 0,1
                h1[nt] = *(const uint4*)(p +  16);   // bh chunks 2,3
                l0[nt] = *(const uint4*)(p + 128);   // bl chunks 0,1
                l1[nt] = *(const uint4*)(p + 144);   // bl chunks 2,3
            }
            // main: zh * bh   (K=64, 8 MMAs)
            mma16(am[0], zh[0], h0[0].x, h0[0].y);
            mma16(am[1], zh[0], h0[1].x, h0[1].y);
            mma16(am[0], zh[1], h0[0].z, h0[0].w);
            mma16(am[1], zh[1], h0[1].z, h0[1].w);
            mma16(am[0], zh[2], h1[0].x, h1[0].y);
            mma16(am[1], zh[2], h1[1].x, h1[1].y);
            mma16(am[0], zh[3], h1[0].z, h1[0].w);
            mma16(am[1], zh[3], h1[1].z, h1[1].w);
            // corr pass 1: zh * bl'  (8 MMAs)
            mma16(ac[0], zh[0], l0[0].x, l0[0].y);
            mma16(ac[1], zh[0], l0[1].x, l0[1].y);
            mma16(ac[0], zh[1], l0[0].z, l0[0].w);
            mma16(ac[1], zh[1], l0[1].z, l0[1].w);
            mma16(ac[0], zh[2], l1[0].x, l1[0].y);
            mma16(ac[1], zh[2], l1[1].x, l1[1].y);
            mma16(ac[0], zh[3], l1[0].z, l1[0].w);
            mma16(ac[1], zh[3], l1[1].z, l1[1].w);
            // corr pass 2: zl' * bh  (8 MMAs, same 2^-17 scale)
            mma16(ac[0], zl[0], h0[0].x, h0[0].y);
            mma16(ac[1], zl[0], h0[1].x, h0[1].y);
            mma16(ac[0], zl[1], h0[0].z, h0[0].w);
            mma16(ac[1], zl[1], h0[1].z, h0[1].w);
            mma16(ac[0], zl[2], h1[0].x, h1[0].y);
            mma16(ac[1], zl[2], h1[1].x, h1[1].y);
            mma16(ac[0], zl[3], h1[0].z, h1[0].w);
            mma16(ac[1], zl[3], h1[1].z, h1[1].w);

            // epilogue: acc -> rows (g=class0, g+8=class1), cols 2tg, 2tg+1
#pragma unroll
            for (int nt = 0; nt < 2; nt++) {
                int kc = st * CHUNK + sub * 16 + nt * 8 + 2 * tg;
                float2 sn = *(const float2*)&snm[kc];
                // dot = RN(main*2^-6 + corr*2^-17)  (mul exact, fma 1 round)
                float d0 = fmaf(ac[nt][0], 0x1p-17f, am[nt][0] * 0x1p-6f);
                float d1 = fmaf(ac[nt][1], 0x1p-17f, am[nt][1] * 0x1p-6f);
                float d2 = fmaf(ac[nt][2], 0x1p-17f, am[nt][2] * 0x1p-6f);
                float d3 = fmaf(ac[nt][3], 0x1p-17f, am[nt][3] * 0x1p-6f);
                // reference rounding: t = RN(Z+E); s = RN(t - 2*dot)
                float s0 = fmaf(-2.f, d0, zn[0] + sn.x);
                float s1 = fmaf(-2.f, d1, zn[0] + sn.y);
                float s2 = fmaf(-2.f, d2, zn[1] + sn.x);
                float s3 = fmaf(-2.f, d3, zn[1] + sn.y);
                ull p;  // s > 0 -> float bits order-monotone; low idx wins
                p = ((ull)__float_as_uint(s0) << 32) | (unsigned)kc;
                if (p < best[0]) best[0] = p;
                p = ((ull)__float_as_uint(s1) << 32) | (unsigned)(kc + 1);
                if (p < best[0]) best[0] = p;
                p = ((ull)__float_as_uint(s2) << 32) | (unsigned)kc;
                if (p < best[1]) best[1] = p;
                p = ((ull)__float_as_uint(s3) << 32) | (unsigned)(kc + 1);
                if (p < best[1]) best[1] = p;
            }
        }
        __syncthreads();       // done reading buf before it is re-staged
    }

    // ---- quad allreduce of the 2 row-class results ----
#pragma unroll
    for (int c = 0; c < 2; c++) {
        ull o = __shfl_xor_sync(0xffffffffu, best[c], 1);
        if (o < best[c]) best[c] = o;
        o = __shfl_xor_sync(0xffffffffu, best[c], 2);
        if (o < best[c]) best[c] = o;
    }

    // lanes tg<2 write outputs: lane handles row class tg (query qb+tg*8+g)
    float sq = 0.f;
    if (tg < 2) {
        const int q = qb + tg * 8 + g;
        const int base = zbase[tg];
        const int bk = (int)(unsigned)(best[tg] & 0xffffffffull);
        const float4* code4 = (const float4*)(cbm + bk * 64);
#pragma unroll
        for (int j = 0; j < 16; j++) {
            float4 cv = code4[j];
            float z0 = z[base + (4 * j + 0) * 1024];
            float z1 = z[base + (4 * j + 1) * 1024];
            float z2 = z[base + (4 * j + 2) * 1024];
            float z3 = z[base + (4 * j + 3) * 1024];
            float d0 = cv.x - z0, d1 = cv.y - z1, d2 = cv.z - z2, d3 = cv.w - z3;
            sq += d0 * d0 + d1 * d1 + d2 * d2 + d3 * d3;
            out[base + (4 * j + 0) * 1024] = cv.x;
            out[base + (4 * j + 1) * 1024] = cv.y;
            out[base + (4 * j + 2) * 1024] = cv.z;
            out[base + (4 * j + 3) * 1024] = cv.w;
        }
        out[IDX_OFF + m * NQ + q] = (float)bk;
        atomicAdd(out + BIN_OFF + bk, 1.0f);
    }

    // loss = 1.25 * sum(diff^2) / (NQ*ED)
#pragma unroll
    for (int o = 16; o > 0; o >>= 1)
        sq += __shfl_down_sync(0xffffffffu, sq, o);
    if (lane == 0) red[warp] = sq;
    __syncthreads();
    if (tid == 0) {
        float s = ((red[0] + red[1]) + (red[2] + red[3])) +
                  ((red[4] + red[5]) + (red[6] + red[7]));
        atomicAdd(out + LOSS_OFF, s * (1.25f / (float)(NQ * ED)));
    }
}

extern "C" void kernel_launch(void* const* d_in, const int* in_sizes, int n_in,
                              void* d_out, int out_size) {
    const float* z  = (const float*)d_in[0];
    const float* cb = (const float*)d_in[1];
    float* out = (float*)d_out;

    cudaFuncSetAttribute(vq_mma, cudaFuncAttributeMaxDynamicSharedMemorySize,
                         SMEM_TOTAL);
    vq_init<<<1, 1024>>>(out);
    vq_pack<<<NM * NE * 4 / 256, 256>>>(cb);
    vq_snorm<<<NM * NE / 256, 256>>>(cb);
    dim3 grid(NM, NQ / 128);
    vq_mma<<<grid, 256, SMEM_TOTAL>>>(z, cb, out);
}